// round 13
// baseline (speedup 1.0000x reference)
#include <cuda_runtime.h>
#include <math.h>

#define BATCH 8
#define CCH   256
#define CIN   512
#define HH    128
#define WW    128
#define PLANE (HH*WW)
#define KC      32
#define ASTRIDE 36
#define BSTRIDE 136
#define SMEM_FLOATS (2*CCH*ASTRIDE + 2*KC*BSTRIDE)
#define SMEM_BYTES  (SMEM_FLOATS*4)

// static device scratch (no allocations anywhere)
__device__ float g_Fm[(size_t)BATCH*CCH*HH*WW];
__device__ float g_Wp[9*CCH*CIN];
__device__ float g_m1avg[BATCH*CCH], g_m1max[BATCH*CCH];
__device__ float g_colsum[BATCH*CCH*WW], g_rowsum[BATCH*CCH*HH];
__device__ float g_m2avg[BATCH*WW], g_m2max[BATCH*WW];
__device__ float g_m3avg[BATCH*HH], g_m3max[BATCH*HH];
__device__ float g_coef[36];
__device__ float g_U1[BATCH*CCH*4], g_U2[BATCH*WW*4], g_U3[BATCH*HH*4];
__device__ float g_V1[BATCH*CCH*4];
__device__ float g_gavg[BATCH*CCH], g_gmax[BATCH*CCH], g_spec[BATCH*CCH];

__device__ __forceinline__ float tf32r(float x) {
    unsigned u; asm("cvt.rna.tf32.f32 %0, %1;" : "=r"(u) : "f"(x));
    return __uint_as_float(u);
}
__device__ __forceinline__ void atomicMaxF(float* addr, float v) {
    int* ia = (int*)addr; int old = __float_as_int(*addr);
    while (__int_as_float(old) < v) {
        int prev = atomicCAS(ia, old, __float_as_int(v));
        if (prev == old) break; old = prev;
    }
}
__device__ __forceinline__ float sigmoidf(float x) { return 1.0f/(1.0f+expf(-x)); }

// conv weight prep: [o][ci][kh][kw] -> g_Wp[tap][o][ci], tf32-rounded
__global__ void k_prep_w(const float* __restrict__ w) {
    int e = blockIdx.x*256 + threadIdx.x;
    int tap = e/(CCH*CIN); int rem = e - tap*(CCH*CIN);
    int o = rem>>9, ci = rem&511;
    int kh = tap/3, kw = tap - kh*3;
    g_Wp[e] = tf32r(w[((o*CIN+ci)*3+kh)*3+kw]);
}

__global__ void k_init_minmax() {
    int i = blockIdx.x*256 + threadIdx.x;
    if (i < BATCH*WW) g_m2max[i] = -3.0e38f;
    if (i < BATCH*HH) g_m3max[i] = -3.0e38f;
}

// conv3x3 SAME + bias + LeakyReLU via mma.sync tf32. block=(h,b), out tile 256x128.
__global__ void __launch_bounds__(256, 1)
k_conv(const float* __restrict__ frm, const float* __restrict__ oth,
       const float* __restrict__ bias) {
    extern __shared__ float smem[];
    float* As = smem;                      // 2 x [256][36]
    float* Bs = smem + 2*CCH*ASTRIDE;      // 2 x [32][136], data at col 4+w, zeros at 3/132

    const int h = blockIdx.x, b = blockIdx.y;
    const int tid = threadIdx.x, warp = tid>>5, lane = tid&31;
    const int g = lane>>2, tg = lane&3;
    const int wm = warp&3, wn = warp>>2;

    float acc[4][8][4];
#pragma unroll
    for (int i=0;i<4;i++)
#pragma unroll
    for (int j=0;j<8;j++)
#pragma unroll
    for (int q=0;q<4;q++) acc[i][j][q]=0.f;

    float4 areg[8]; float4 breg[4];

    auto ldA = [&](int tap, int cc) {
        const float* base = g_Wp + (size_t)tap*(CCH*CIN);
#pragma unroll
        for (int j=0;j<8;j++) {
            int f4 = j*256+tid, row = f4>>3, col = f4&7;
            areg[j] = *(const float4*)(base + row*CIN + cc + col*4);
        }
    };
    auto stA = [&](float* dst) {
#pragma unroll
        for (int j=0;j<8;j++) {
            int f4 = j*256+tid, row = f4>>3, col = f4&7;
            *(float4*)(dst + row*ASTRIDE + col*4) = areg[j];
        }
    };
    auto ldB = [&](int r, int cc) {
#pragma unroll
        for (int j=0;j<4;j++) {
            int f4 = j*256+tid, ch = f4>>5, cw = f4&31;
            float4 v = make_float4(0.f,0.f,0.f,0.f);
            if (r >= 0 && r < HH) {
                int ci = cc + ch;
                const float* src = (ci < 256)
                    ? (frm + (((size_t)(b*256+ci)*HH + r)*WW))
                    : (oth + (((size_t)(b*256+ci-256)*HH + r)*WW));
                v = *(const float4*)(src + cw*4);
            }
            breg[j] = v;
        }
    };
    auto stB = [&](float* dst) {
#pragma unroll
        for (int j=0;j<4;j++) {
            int f4 = j*256+tid, ch = f4>>5, cw = f4&31;
            float4 v = breg[j];
            v.x=tf32r(v.x); v.y=tf32r(v.y); v.z=tf32r(v.z); v.w=tf32r(v.w);
            *(float4*)(dst + ch*BSTRIDE + 4 + cw*4) = v;
        }
        if (tid < KC) { dst[tid*BSTRIDE+3]=0.f; dst[tid*BSTRIDE+132]=0.f; }
    };

    ldA(0,0); ldB(h-1,0);
    stA(As); stB(Bs);
    __syncthreads();

    for (int s=0; s<144; s++) {
        const int dx = s%3;
        const int nxt = s+1;
        bool haveA = (nxt < 144), haveB = false;
        if (haveA) {
            int ndy = nxt/48, nrem = nxt%48, ndx = nrem%3;
            int ncc = (nrem/3)*KC;
            ldA(ndy*3+ndx, ncc);
            if (nrem%3 == 0) { haveB = true; ldB(h+ndy-1, ncc); }
        }
        const float* Ac = As + (s&1)*(CCH*ASTRIDE);
        const float* Bc = Bs + ((s/3)&1)*(KC*BSTRIDE);

#pragma unroll
        for (int ks=0; ks<4; ks++) {
            unsigned af[4][4], bf[8][2];
            const int kcol = ks*8 + tg;
#pragma unroll
            for (int mi=0; mi<4; mi++) {
                int m0 = wm*64 + mi*16 + g;
                af[mi][0] = __float_as_uint(Ac[ m0   *ASTRIDE + kcol   ]);
                af[mi][1] = __float_as_uint(Ac[(m0+8)*ASTRIDE + kcol   ]);
                af[mi][2] = __float_as_uint(Ac[ m0   *ASTRIDE + kcol+4 ]);
                af[mi][3] = __float_as_uint(Ac[(m0+8)*ASTRIDE + kcol+4 ]);
            }
#pragma unroll
            for (int ni=0; ni<8; ni++) {
                int n = wn*64 + ni*8 + g;
                bf[ni][0] = __float_as_uint(Bc[(kcol  )*BSTRIDE + 3 + n + dx]);
                bf[ni][1] = __float_as_uint(Bc[(kcol+4)*BSTRIDE + 3 + n + dx]);
            }
#pragma unroll
            for (int mi=0; mi<4; mi++)
#pragma unroll
            for (int ni=0; ni<8; ni++) {
                asm volatile(
                    "mma.sync.aligned.m16n8k8.row.col.f32.tf32.tf32.f32 "
                    "{%0,%1,%2,%3}, {%4,%5,%6,%7}, {%8,%9}, {%0,%1,%2,%3};\n"
                    : "+f"(acc[mi][ni][0]), "+f"(acc[mi][ni][1]),
                      "+f"(acc[mi][ni][2]), "+f"(acc[mi][ni][3])
                    : "r"(af[mi][0]), "r"(af[mi][1]), "r"(af[mi][2]), "r"(af[mi][3]),
                      "r"(bf[ni][0]), "r"(bf[ni][1]));
            }
        }
        if (haveA) stA(As + ((s+1)&1)*(CCH*ASTRIDE));
        if (haveB) stB(Bs + (((s+1)/3)&1)*(KC*BSTRIDE));
        __syncthreads();
    }

#pragma unroll
    for (int mi=0; mi<4; mi++) {
        int m0 = wm*64 + mi*16 + g;
        float b0v = bias[m0], b1v = bias[m0+8];
#pragma unroll
        for (int ni=0; ni<8; ni++) {
            int w0 = wn*64 + ni*8 + tg*2;
            float v0 = acc[mi][ni][0] + b0v; v0 = (v0>=0.f)?v0:0.01f*v0;
            float v1 = acc[mi][ni][1] + b0v; v1 = (v1>=0.f)?v1:0.01f*v1;
            float v2 = acc[mi][ni][2] + b1v; v2 = (v2>=0.f)?v2:0.01f*v2;
            float v3 = acc[mi][ni][3] + b1v; v3 = (v3>=0.f)?v3:0.01f*v3;
            size_t base0 = (((size_t)(b*CCH+m0  )*HH)+h)*WW + w0;
            size_t base1 = (((size_t)(b*CCH+m0+8)*HH)+h)*WW + w0;
            *(float2*)(g_Fm+base0) = make_float2(v0,v1);
            *(float2*)(g_Fm+base1) = make_float2(v2,v3);
        }
    }
}

// per-(b,c) plane reductions: mode1 avg/max; col sums + m2max; row sums + m3max
__global__ void k_reduce() {
    const int bc = blockIdx.x, b = bc>>8;
    const float* plane = g_Fm + (size_t)bc*PLANE;
    const int tid = threadIdx.x, w = tid>>5, lane = tid&31;

    float cs0=0.f,cs1=0.f,cs2=0.f,cs3=0.f;
    float cm0=-3.0e38f,cm1=-3.0e38f,cm2=-3.0e38f,cm3=-3.0e38f;
    float psum=0.f, pmax=-3.0e38f;

    for (int hh=0; hh<16; hh++) {
        int h = w*16 + hh;
        const float* row = plane + h*WW;
        float v0=row[lane], v1=row[lane+32], v2=row[lane+64], v3=row[lane+96];
        float rs = v0+v1+v2+v3;
        float rm = fmaxf(fmaxf(v0,v1), fmaxf(v2,v3));
        psum += rs; pmax = fmaxf(pmax, rm);
        cs0+=v0; cs1+=v1; cs2+=v2; cs3+=v3;
        cm0=fmaxf(cm0,v0); cm1=fmaxf(cm1,v1); cm2=fmaxf(cm2,v2); cm3=fmaxf(cm3,v3);
#pragma unroll
        for (int o=16; o>0; o>>=1) {
            rs += __shfl_xor_sync(0xffffffffu, rs, o);
            rm  = fmaxf(rm, __shfl_xor_sync(0xffffffffu, rm, o));
        }
        if (lane == 0) {
            g_rowsum[bc*HH + h] = rs;
            atomicMaxF(&g_m3max[b*HH + h], rm);
        }
    }

    __shared__ float scol[8][128], scolm[8][128];
    scol[w][lane]=cs0; scol[w][lane+32]=cs1; scol[w][lane+64]=cs2; scol[w][lane+96]=cs3;
    scolm[w][lane]=cm0; scolm[w][lane+32]=cm1; scolm[w][lane+64]=cm2; scolm[w][lane+96]=cm3;
    __syncthreads();
    if (tid < 128) {
        float s=0.f, m=-3.0e38f;
#pragma unroll
        for (int i=0;i<8;i++) { s += scol[i][tid]; m = fmaxf(m, scolm[i][tid]); }
        g_colsum[bc*WW + tid] = s;
        atomicMaxF(&g_m2max[b*WW + tid], m);
    }

#pragma unroll
    for (int o=16; o>0; o>>=1) {
        psum += __shfl_xor_sync(0xffffffffu, psum, o);
        pmax  = fmaxf(pmax, __shfl_xor_sync(0xffffffffu, pmax, o));
    }
    __shared__ float rs8[8], rm8[8];
    if (lane == 0) { rs8[w]=psum; rm8[w]=pmax; }
    __syncthreads();
    if (tid == 0) {
        float s=0.f, m=-3.0e38f;
#pragma unroll
        for (int i=0;i<8;i++) { s += rs8[i]; m = fmaxf(m, rm8[i]); }
        g_m1avg[bc] = s*(1.0f/16384.0f);
        g_m1max[bc] = m;
    }
}

__global__ void k_reduce2() {
    int id = blockIdx.x*256 + threadIdx.x;   // 0..1023
    int b = id>>7, x = id&127;
    float s = 0.f;
    for (int c=0;c<CCH;c++) s += g_colsum[(b*CCH+c)*WW + x];
    g_m2avg[id] = s*(1.0f/32768.0f);
    s = 0.f;
    for (int c=0;c<CCH;c++) s += g_rowsum[(b*CCH+c)*HH + x];
    g_m3avg[id] = s*(1.0f/32768.0f);
}

// fold adapter+U_gen: logits_k = wA[k]*avg + wM[k]*mx + c0[k]
__global__ void k_coef(const float* a1w, const float* a1b, const float* a2w, const float* a2b,
                       const float* a3w, const float* a3b, const float* ugw, const float* ugb) {
    int j = threadIdx.x;
    if (j >= 36) return;
    const float* aw[3] = { a1w, a2w, a3w };
    const float* ab[3] = { a1b, a2b, a3b };
    int m = j/12, r = (j%12)/4, k = j%4;
    float s = 0.f;
    if (r == 0)      { for (int c=0;c<CCH;c++) s += ugw[k*CCH+c]*aw[m][c*2]; }
    else if (r == 1) { for (int c=0;c<CCH;c++) s += ugw[k*CCH+c]*aw[m][c*2+1]; }
    else             { for (int c=0;c<CCH;c++) s += ugw[k*CCH+c]*ab[m][c]; s += ugb[k]; }
    g_coef[j] = s;
}

__global__ void k_U() {
    int id = blockIdx.x*256 + threadIdx.x;   // 0..4095
    float avg, mx; float* out; int m;
    if (id < 2048)      { avg=g_m1avg[id];      mx=g_m1max[id];      out=g_U1+id*4;        m=0; }
    else if (id < 3072) { int i=id-2048; avg=g_m2avg[i]; mx=g_m2max[i]; out=g_U2+i*4;      m=1; }
    else                { int i=id-3072; avg=g_m3avg[i]; mx=g_m3max[i]; out=g_U3+i*4;      m=2; }
    float lg[4], mxl = -3.0e38f;
#pragma unroll
    for (int k=0;k<4;k++) {
        lg[k] = g_coef[m*12+k]*avg + g_coef[m*12+4+k]*mx + g_coef[m*12+8+k];
        mxl = fmaxf(mxl, lg[k]);
    }
    float s = 0.f;
#pragma unroll
    for (int k=0;k<4;k++) { lg[k] = expf(lg[k]-mxl); s += lg[k]; }
    float inv = 1.0f/s;
#pragma unroll
    for (int k=0;k<4;k++) out[k] = lg[k]*inv;
}

__global__ void k_V1(const float* __restrict__ rw) {
    int i = blockIdx.x*256 + threadIdx.x;    // 0..8191
    int b = i>>10, o = (i>>2)&255, k = i&3;
    float s = 0.f;
    for (int c=0;c<CCH;c++) s += rw[o*CCH+c]*g_U1[(b*CCH+c)*4+k];
    g_V1[i] = s;
}

// spectral stats: g_avg / g_max over F_spe[b,c,n] = U1 . U23
__global__ void k_spec1() {
    int b = blockIdx.x, c = threadIdx.x;
    __shared__ float su[256][4];
#pragma unroll
    for (int k=0;k<4;k++)
        su[c][k] = (c < 128) ? g_U2[(b*128+c)*4+k] : g_U3[(b*128+(c-128))*4+k];
    __syncthreads();
    float u1[4];
#pragma unroll
    for (int k=0;k<4;k++) u1[k] = g_U1[(b*CCH+c)*4+k];
    float s = 0.f, m = -3.0e38f;
    for (int n=0;n<256;n++) {
        float d = u1[0]*su[n][0]+u1[1]*su[n][1]+u1[2]*su[n][2]+u1[3]*su[n][3];
        s += d; m = fmaxf(m, d);
    }
    g_gavg[b*CCH+c] = s*(1.0f/256.0f);
    g_gmax[b*CCH+c] = m;
}

__global__ void k_spec2(const float* spa_w, const float* spa_b,
                        const float* spm_w, const float* spm_b) {
    int i = blockIdx.x*256 + threadIdx.x;    // 0..2047
    int b = i>>8, o = i&255;
    float s = spa_b[o] + spm_b[o];
    for (int c=0;c<CCH;c++)
        s += g_gavg[b*CCH+c]*spa_w[o*CCH+c] + g_gmax[b*CCH+c]*spm_w[o*CCH+c];
    g_spec[i] = sigmoidf(sigmoidf(s));
}

// final: fused = a*Watt*frm + (1-a)*(1-Watt)*oth ; cp = V1.(U2*U3) + recon_b
__global__ void __launch_bounds__(256)
k_final(const float* __restrict__ frm, const float* __restrict__ oth,
        const float* __restrict__ recon_b, const float* __restrict__ spw,
        const float* __restrict__ spb, const float* __restrict__ alpha,
        float* __restrict__ out) {
    const int h = blockIdx.x, b = blockIdx.y, tid = threadIdx.x;
    __shared__ float su2[128][4], t[256][4], sspec[256], srb[256], ssa[128];
    float u3[4];
#pragma unroll
    for (int k=0;k<4;k++) u3[k] = g_U3[(b*128+h)*4+k];
    if (tid < 128) {
#pragma unroll
        for (int k=0;k<4;k++) su2[tid][k] = g_U2[(b*128+tid)*4+k];
    }
#pragma unroll
    for (int k=0;k<4;k++) t[tid][k] = g_V1[(b*CCH+tid)*4+k]*u3[k];
    sspec[tid] = g_spec[b*CCH+tid];
    srb[tid] = recon_b[tid];
    __syncthreads();
    if (tid < 128) {
        float d = u3[0]*su2[tid][0]+u3[1]*su2[tid][1]+u3[2]*su2[tid][2]+u3[3]*su2[tid][3];
        ssa[tid] = sigmoidf(spw[0]*d + spb[0]);
    }
    __syncthreads();
    const float a = alpha[0];
    const size_t N = (size_t)BATCH*CCH*HH*WW;
    for (int it=0; it<128; it++) {
        int l = it*256 + tid;
        int c = l>>7, w = l&127;
        size_t addr = (((size_t)(b*CCH+c)*HH)+h)*WW + w;
        float f = frm[addr], o = oth[addr];
        float cp = t[c][0]*su2[w][0]+t[c][1]*su2[w][1]+t[c][2]*su2[w][2]+t[c][3]*su2[w][3] + srb[c];
        float Watt = sspec[c]*ssa[w];
        out[addr]     = a*Watt*f + (1.0f-a)*(1.0f-Watt)*o;
        out[N + addr] = cp;
    }
}

extern "C" void kernel_launch(void* const* d_in, const int* in_sizes, int n_in,
                              void* d_out, int out_size) {
    const float* frm  = (const float*)d_in[0];
    const float* oth  = (const float*)d_in[1];
    const float* cw   = (const float*)d_in[2];
    const float* cb   = (const float*)d_in[3];
    const float* a1w  = (const float*)d_in[4];
    const float* a1b  = (const float*)d_in[5];
    const float* a2w  = (const float*)d_in[6];
    const float* a2b  = (const float*)d_in[7];
    const float* a3w  = (const float*)d_in[8];
    const float* a3b  = (const float*)d_in[9];
    const float* ugw  = (const float*)d_in[10];
    const float* ugb  = (const float*)d_in[11];
    const float* rw   = (const float*)d_in[12];
    const float* rb   = (const float*)d_in[13];
    const float* spw  = (const float*)d_in[14];
    const float* spb  = (const float*)d_in[15];
    const float* spaw = (const float*)d_in[16];
    const float* spab = (const float*)d_in[17];
    const float* spmw = (const float*)d_in[18];
    const float* spmb = (const float*)d_in[19];
    const float* alph = (const float*)d_in[20];
    float* out = (float*)d_out;

    cudaFuncSetAttribute(k_conv, cudaFuncAttributeMaxDynamicSharedMemorySize, SMEM_BYTES);

    k_prep_w<<<4608, 256>>>(cw);
    k_init_minmax<<<4, 256>>>();
    k_conv<<<dim3(HH, BATCH), 256, SMEM_BYTES>>>(frm, oth, cb);
    k_reduce<<<BATCH*CCH, 256>>>();
    k_reduce2<<<4, 256>>>();
    k_coef<<<1, 64>>>(a1w, a1b, a2w, a2b, a3w, a3b, ugw, ugb);
    k_U<<<16, 256>>>();
    k_V1<<<32, 256>>>(rw);
    k_spec1<<<BATCH, 256>>>();
    k_spec2<<<8, 256>>>(spaw, spab, spmw, spmb);
    k_final<<<dim3(HH, BATCH), 256>>>(frm, oth, rb, spw, spb, alph, out);
}